// round 3
// baseline (speedup 1.0000x reference)
#include <cuda_runtime.h>
#include <math.h>

#define N_NODES 100000
#define N_EDGES 1200000
#define F_IN 128
#define H 64
#define C 40
#define NB_SCAN 391   // ceil(100000/256)
#define NPB 32        // nodes per block in layer kernels

// ---------------- scratch (device globals; no allocs allowed) ----------------
__device__ int   g_is64;
__device__ int   g_deg[N_NODES];
__device__ int   g_off[N_NODES];
__device__ int   g_cur[N_NODES];
__device__ int   g_bsum[NB_SCAN];
__device__ float g_dinv[N_NODES];
__device__ int   g_csrc[N_EDGES];
__device__ float g_h1[(size_t)N_NODES * H];   // dinv * (x @ W1)      ("h1'")
__device__ float g_h2[(size_t)N_NODES * H];   // dinv * (relu(..)@W2) ("h2'")

// ---------------- zero degrees + int64-vs-int32 detection ----------------
__global__ void k_pre(const void* ei) {
    int i = blockIdx.x * blockDim.x + threadIdx.x;
    if (i < N_NODES) g_deg[i] = 0;
    if (i == 0) {
        const long long* p = (const long long*)ei;
        int ok = 1;
        for (int t = 0; t < 64; ++t) {
            long long v = p[t];
            if (v < 0 || v >= N_NODES) { ok = 0; break; }
        }
        g_is64 = ok;
    }
}

__device__ __forceinline__ int load_idx(const void* ei, int pos, int which) {
    if (g_is64) return (int)((const long long*)ei)[(size_t)which * N_EDGES + pos];
    return ((const int*)ei)[(size_t)which * N_EDGES + pos];
}

__global__ void k_hist(const void* __restrict__ ei) {
    int e = blockIdx.x * blockDim.x + threadIdx.x;
    if (e < N_EDGES) atomicAdd(&g_deg[load_idx(ei, e, 1)], 1);
}

// ---------------- exclusive scan of degrees + dinv ----------------
__global__ void __launch_bounds__(256) k_scan1() {
    int i = blockIdx.x * 256 + threadIdx.x;
    int v = (i < N_NODES) ? g_deg[i] : 0;
    int lane = threadIdx.x & 31, w = threadIdx.x >> 5;
    int incl = v;
#pragma unroll
    for (int o = 1; o < 32; o <<= 1) {
        int t = __shfl_up_sync(0xffffffffu, incl, o);
        if (lane >= o) incl += t;
    }
    __shared__ int ws[8];
    if (lane == 31) ws[w] = incl;
    __syncthreads();
    if (w == 0 && lane < 8) {
        int t = ws[lane];
        int inc = t;
#pragma unroll
        for (int o = 1; o < 8; o <<= 1) {
            int u = __shfl_up_sync(0xffu, inc, o);
            if (lane >= o) inc += u;
        }
        ws[lane] = inc - t;
    }
    __syncthreads();
    int excl = incl - v + ws[w];
    if (i < N_NODES) {
        g_off[i] = excl;
        g_dinv[i] = rsqrtf((float)(v + 1));
    }
    if (threadIdx.x == 255) g_bsum[blockIdx.x] = excl + v;
}

__global__ void __launch_bounds__(512) k_scan2() {
    __shared__ int buf[512];
    int t = threadIdx.x;
    int v = (t < NB_SCAN) ? g_bsum[t] : 0;
    buf[t] = v;
    __syncthreads();
    for (int o = 1; o < 512; o <<= 1) {
        int u = (t >= o) ? buf[t - o] : 0;
        __syncthreads();
        buf[t] += u;
        __syncthreads();
    }
    if (t < NB_SCAN) g_bsum[t] = buf[t] - v;
}

__global__ void __launch_bounds__(256) k_scan3() {
    int i = blockIdx.x * 256 + threadIdx.x;
    if (i < N_NODES) {
        int o = g_off[i] + g_bsum[blockIdx.x];
        g_off[i] = o;
        g_cur[i] = o;
    }
}

// ---------------- CSR scatter (int atomics only) ----------------
__global__ void k_scatter(const void* __restrict__ ei) {
    int e = blockIdx.x * blockDim.x + threadIdx.x;
    if (e < N_EDGES) {
        int s = load_idx(ei, e, 0);
        int d = load_idx(ei, e, 1);
        int pos = atomicAdd(&g_cur[d], 1);
        g_csrc[pos] = s;
    }
}

// ---------------- GEMM1: g_h1 = dinv * (x @ W1) ----------------
__global__ void __launch_bounds__(256) k_gemm1(const float* __restrict__ x,
                                               const float* __restrict__ W1) {
    __shared__ float Ws[F_IN * H];
    int tid = threadIdx.x;
#pragma unroll
    for (int i = 0; i < (F_IN * H) / 256; ++i) Ws[tid + i * 256] = W1[tid + i * 256];
    __syncthreads();

    int r  = blockIdx.x * 16 + (tid >> 4);
    int cg = (tid & 15) << 2;
    const float4* xr = reinterpret_cast<const float4*>(x + (size_t)r * F_IN);

    float a0 = 0.f, a1 = 0.f, a2 = 0.f, a3 = 0.f;
#pragma unroll
    for (int k4 = 0; k4 < F_IN / 4; ++k4) {
        float4 xv = xr[k4];
        const float* wb = &Ws[(k4 * 4) * H + cg];
        float4 w0 = *(const float4*)(wb);
        float4 w1 = *(const float4*)(wb + H);
        float4 w2 = *(const float4*)(wb + 2 * H);
        float4 w3 = *(const float4*)(wb + 3 * H);
        a0 += xv.x * w0.x; a1 += xv.x * w0.y; a2 += xv.x * w0.z; a3 += xv.x * w0.w;
        a0 += xv.y * w1.x; a1 += xv.y * w1.y; a2 += xv.y * w1.z; a3 += xv.y * w1.w;
        a0 += xv.z * w2.x; a1 += xv.z * w2.y; a2 += xv.z * w2.z; a3 += xv.z * w2.w;
        a0 += xv.w * w3.x; a1 += xv.w * w3.y; a2 += xv.w * w3.z; a3 += xv.w * w3.w;
    }
    float dv = g_dinv[r];
    *(float4*)&g_h1[(size_t)r * H + cg] =
        make_float4(dv * a0, dv * a1, dv * a2, dv * a3);
}

// ---------------- shared aggregation helper: acc = h'[n] + sum h'[src] -------
__device__ __forceinline__ float2 aggregate(const float* __restrict__ hp,
                                            int n, int c) {
    float2 acc = *(const float2*)&hp[(size_t)n * H + c];
    int row = g_off[n], deg = g_deg[n];
    const int* ep = g_csrc + row;
    int j = 0;
    for (; j + 4 <= deg; j += 4) {
        int s0 = ep[j], s1 = ep[j + 1], s2 = ep[j + 2], s3 = ep[j + 3];
        float2 v0 = *(const float2*)&hp[(size_t)s0 * H + c];
        float2 v1 = *(const float2*)&hp[(size_t)s1 * H + c];
        float2 v2 = *(const float2*)&hp[(size_t)s2 * H + c];
        float2 v3 = *(const float2*)&hp[(size_t)s3 * H + c];
        acc.x += (v0.x + v1.x) + (v2.x + v3.x);
        acc.y += (v0.y + v1.y) + (v2.y + v3.y);
    }
    for (; j < deg; ++j) {
        int s = ep[j];
        float2 v = *(const float2*)&hp[(size_t)s * H + c];
        acc.x += v.x;
        acc.y += v.y;
    }
    return acc;
}

// ---------------- layer1: aggregate h1' -> relu(di*acc + b1) -> @W2 -> h2' ---
__global__ void __launch_bounds__(256) k_layer1(const float* __restrict__ W2,
                                                const float* __restrict__ b1) {
    __shared__ float W2s[H * H];   // 16 KB
    __shared__ float b1s[H];
    __shared__ float aS[NPB][H];   // 8 KB
    int tid = threadIdx.x;
#pragma unroll
    for (int i = 0; i < (H * H) / 256; ++i) W2s[tid + i * 256] = W2[tid + i * 256];
    if (tid < H) b1s[tid] = b1[tid];
    __syncthreads();

    int w = tid >> 5, lane = tid & 31;
    int c = lane << 1;
    int base = blockIdx.x * NPB + w * 4;

    // Phase A: aggregation, warp handles 4 nodes
#pragma unroll
    for (int i = 0; i < 4; ++i) {
        int n = base + i;
        float2 acc = aggregate(g_h1, n, c);
        float di = g_dinv[n];
        aS[w * 4 + i][c]     = fmaxf(di * acc.x + b1s[c], 0.f);
        aS[w * 4 + i][c + 1] = fmaxf(di * acc.y + b1s[c + 1], 0.f);
    }
    __syncthreads();

    // Phase B: 4-node matvec, W2 read amortized over 4 nodes
    float o0[4] = {0.f, 0.f, 0.f, 0.f};
    float o1[4] = {0.f, 0.f, 0.f, 0.f};
#pragma unroll
    for (int k = 0; k < H; ++k) {
        float2 wv = *(const float2*)&W2s[k * H + c];
#pragma unroll
        for (int i = 0; i < 4; ++i) {
            float a = aS[w * 4 + i][k];
            o0[i] += a * wv.x;
            o1[i] += a * wv.y;
        }
    }
#pragma unroll
    for (int i = 0; i < 4; ++i) {
        int n = base + i;
        float dn = g_dinv[n];
        *(float2*)&g_h2[(size_t)n * H + c] = make_float2(dn * o0[i], dn * o1[i]);
    }
}

// ---------------- layer2: aggregate h2' -> +b2 -> emb, @Wc+bc, softmax, argmax
__global__ void __launch_bounds__(256) k_layer2(const float* __restrict__ b2,
                                                const float* __restrict__ Wc,
                                                const float* __restrict__ bc,
                                                float* __restrict__ out) {
    __shared__ float WcS[H * C];   // 10.24 KB
    __shared__ float b2s[H];
    __shared__ float bcs[C];
    __shared__ float eS[NPB][H];   // 8 KB
    int tid = threadIdx.x;
    for (int i = tid; i < H * C; i += 256) WcS[i] = Wc[i];
    if (tid < H) b2s[tid] = b2[tid];
    if (tid < C) bcs[tid] = bc[tid];
    __syncthreads();

    int w = tid >> 5, lane = tid & 31;
    int c = lane << 1;
    int base = blockIdx.x * NPB + w * 4;

    const size_t embOff  = (size_t)N_NODES * C;
    const size_t softOff = embOff + (size_t)N_NODES * H;
    const size_t hardOff = softOff + (size_t)N_NODES * C;

    // Phase A: aggregation + emb
#pragma unroll
    for (int i = 0; i < 4; ++i) {
        int n = base + i;
        float2 acc = aggregate(g_h2, n, c);
        float di = g_dinv[n];
        float e0 = di * acc.x + b2s[c];
        float e1 = di * acc.y + b2s[c + 1];
        *(float2*)(out + embOff + (size_t)n * H + c) = make_float2(e0, e1);
        eS[w * 4 + i][c]     = e0;
        eS[w * 4 + i][c + 1] = e1;
    }
    __syncthreads();

    // Phase B: logits for 4 nodes, Wc read amortized
    float l0[4], l1[4];
#pragma unroll
    for (int i = 0; i < 4; ++i) {
        l0[i] = bcs[lane];
        l1[i] = (lane < 8) ? bcs[lane + 32] : 0.f;
    }
#pragma unroll
    for (int k = 0; k < H; ++k) {
        float wc0 = WcS[k * C + lane];
        float wc1 = (lane < 8) ? WcS[k * C + lane + 32] : 0.f;
#pragma unroll
        for (int i = 0; i < 4; ++i) {
            float e = eS[w * 4 + i][k];
            l0[i] += e * wc0;
            l1[i] += e * wc1;
        }
    }

#pragma unroll
    for (int i = 0; i < 4; ++i) {
        int n = base + i;
        out[(size_t)n * C + lane] = l0[i];
        if (lane < 8) out[(size_t)n * C + lane + 32] = l1[i];

        float mv = l0[i];
        int   mi = lane;
        if (lane < 8 && l1[i] > mv) { mv = l1[i]; mi = lane + 32; }
#pragma unroll
        for (int o = 16; o; o >>= 1) {
            float ov = __shfl_xor_sync(0xffffffffu, mv, o);
            int   oi = __shfl_xor_sync(0xffffffffu, mi, o);
            if (ov > mv || (ov == mv && oi < mi)) { mv = ov; mi = oi; }
        }
        if (lane == 0) out[hardOff + n] = (float)mi;

        float e0 = expf(l0[i] - mv);
        float e1 = (lane < 8) ? expf(l1[i] - mv) : 0.f;
        float s = e0 + e1;
#pragma unroll
        for (int o = 16; o; o >>= 1) s += __shfl_xor_sync(0xffffffffu, s, o);
        float inv = 1.0f / s;
        out[softOff + (size_t)n * C + lane] = e0 * inv;
        if (lane < 8) out[softOff + (size_t)n * C + lane + 32] = e1 * inv;
    }
}

// ---------------- launch ----------------
extern "C" void kernel_launch(void* const* d_in, const int* in_sizes, int n_in,
                              void* d_out, int out_size) {
    const float* x  = (const float*)d_in[0];
    const void*  ei = d_in[1];
    const float* W1 = (const float*)d_in[2];
    const float* b1 = (const float*)d_in[3];
    const float* W2 = (const float*)d_in[4];
    const float* b2 = (const float*)d_in[5];
    const float* Wc = (const float*)d_in[6];
    const float* bc = (const float*)d_in[7];
    float* out = (float*)d_out;

    k_pre<<<(N_NODES + 255) / 256, 256>>>(ei);
    k_hist<<<(N_EDGES + 255) / 256, 256>>>(ei);
    k_scan1<<<NB_SCAN, 256>>>();
    k_scan2<<<1, 512>>>();
    k_scan3<<<NB_SCAN, 256>>>();
    k_scatter<<<(N_EDGES + 255) / 256, 256>>>(ei);

    k_gemm1<<<N_NODES / 16, 256>>>(x, W1);
    k_layer1<<<N_NODES / NPB, 256>>>(W2, b1);
    k_layer2<<<N_NODES / NPB, 256>>>(b2, Wc, bc, out);
}